// round 11
// baseline (speedup 1.0000x reference)
#include <cuda_runtime.h>
#include <cuda_bf16.h>

// ---------------------------------------------------------------------------
// label_loss: B=4.19M elements -> 3 scalars. Memory-bound (218 MB read).
// R11: champion (R10: LDG float4 2-elem/thread, 6 CTAs/SM, L2-prefetch) with
// prefetch distance 2 + prologue prefetch of iterations 0 and 1.
// R10 evidence: distance-1 prefetch took 41.5 -> 39.1us (demand-starvation
// confirmed; ncu snapshot distrusted -- cache-control flush nukes prefetch).
// Deeper lead hides the prefetch queue's own drain latency + covers the
// cold first iteration. Two windows in flight = ~48MB < 126MB L2.
// ---------------------------------------------------------------------------

#define NBLK 888        // 148 SMs * 6 CTAs -> one wave
#define NTHR 256
#define STRIDE (NBLK * NTHR)

static __device__ float g_part[5][NBLK];   // SoA: coalesced finalize reads
static __device__ int   g_count = 0;       // reset by the finalizing block

__device__ __forceinline__ float4 ldcs4(const float4* p) {
    float4 v;
    asm volatile("ld.global.cs.v4.f32 {%0,%1,%2,%3}, [%4];"
                 : "=f"(v.x), "=f"(v.y), "=f"(v.z), "=f"(v.w) : "l"(p));
    return v;
}

__device__ __forceinline__ int2 ldcs2i(const int2* p) {
    int2 v;
    asm volatile("ld.global.cs.v2.s32 {%0,%1}, [%2];"
                 : "=r"(v.x), "=r"(v.y) : "l"(p));
    return v;
}

// Warp-cooperative L2 prefetch of the window for warp-base pair wb:
// label/est = 12 x 128B lines each, mix = 2 lines. Lane l -> one line.
__device__ __forceinline__ void pf_window(const char* label, const char* est,
                                          const char* mix, int wb, int np,
                                          int lane) {
    if (wb + 32 <= np && lane < 26) {
        const char* pf;
        size_t o48 = (size_t)wb * 48;
        if (lane < 12)      pf = label + o48 + (size_t)lane * 128;
        else if (lane < 24) pf = est   + o48 + (size_t)(lane - 12) * 128;
        else                pf = mix   + (size_t)wb * 8 + (size_t)(lane - 24) * 128;
        asm volatile("prefetch.global.L2 [%0];" :: "l"(pf));
    }
}

__device__ __forceinline__ float angdiff_deg(float x1, float y1, float x2, float y2) {
    // |atan2(y1,x1) - atan2(y2,x2)| wrapped to [0, 180], in degrees.
    float cr = fmaf(y1, x2, -x1 * y2);
    float dt = fmaf(x1, x2,  y1 * y2);
    float p  = fabsf(cr);
    float q  = fabsf(dt);
    float mx = fmaxf(fmaxf(p, q), 1e-38f);
    float mn = fminf(p, q);
    float r  = __fdividef(mn, mx);       // r in [0, 1]
    float t2 = r * r;
    const float D = 57.29577951308232f;  // rad -> deg folded into coefficients
    float pl;
    pl = fmaf(t2, -0.01172120f * D,  0.05265332f * D);
    pl = fmaf(t2, pl,           -0.11643287f * D);
    pl = fmaf(t2, pl,            0.19354346f * D);
    pl = fmaf(t2, pl,           -0.33262347f * D);
    pl = fmaf(t2, pl,            0.99997726f * D);
    float at = r * pl;                   // atan(mn/mx) in degrees, [0, 45]
    float a  = (p > q)      ? (90.0f  - at) : at;
    a        = (dt < 0.0f)  ? (180.0f - a ) : a;
    return a;
}

struct Acc { float S, M, A1, A2; };

__device__ __forceinline__ void proc(
    float l00, float l01, float l10, float l11, float l20, float l21,
    float e0, float e1, float e2, float e3, float e4, float e5,
    int m, Acc& a)
{
    float d0 = e0 - l00, d1 = e1 - l10, d2 = e2 - l20;
    float s11 = fmaf(d2, d2, fmaf(d1, d1, d0 * d0));
    float f0 = e3 - l01, f1 = e4 - l11, f2 = e5 - l21;
    float s22 = fmaf(f2, f2, fmaf(f1, f1, f0 * f0));
    float g0 = e0 - l01, g1 = e1 - l11, g2 = e2 - l21;
    float s12 = fmaf(g2, g2, fmaf(g1, g1, g0 * g0));
    float h0 = e3 - l00, h1 = e4 - l10, h2 = e5 - l20;
    float s21 = fmaf(h2, h2, fmaf(h1, h1, h0 * h0));

    a.S += s11;
    float mixed = fminf(s11 + s22, s12 + s21);  // /3 deferred to finalize
    a.M  += (m != 0) ? mixed : 0.0f;

    float a11 = angdiff_deg(l00, l10, e0, e1);
    float a22 = angdiff_deg(l01, l11, e3, e4);
    float a12 = angdiff_deg(l00, l10, e3, e4);
    float a21 = angdiff_deg(l01, l11, e0, e1);
    bool ud = (a11 + a22) < (a12 + a21);
    a.A1 += ud ? a11 : a12;
    a.A2 += ud ? a22 : a21;
}

__global__ void __launch_bounds__(NTHR, 6)
fused_kernel(const float* __restrict__ label, const float* __restrict__ est,
             const int* __restrict__ mix, float* __restrict__ out, int B)
{
    Acc a{0.f, 0.f, 0.f, 0.f};
    int c0 = 0;
    const float4* L4 = (const float4*)label;
    const float4* E4 = (const float4*)est;
    const int2*   M2 = (const int2*)mix;
    const char* Lc8 = (const char*)label;
    const char* Ec8 = (const char*)est;
    const char* Mc8 = (const char*)mix;
    int np = B >> 1;  // pairs; 2 elements = 3 float4 per array
    const int lane = threadIdx.x & 31;
    const int wb0 = blockIdx.x * NTHR + (threadIdx.x & ~31);  // warp base pair

    // Prologue: prefetch iterations 0 and 1 windows (distance-2 pipeline).
    pf_window(Lc8, Ec8, Mc8, wb0, np, lane);
    pf_window(Lc8, Ec8, Mc8, wb0 + STRIDE, np, lane);

    for (int pi = blockIdx.x * NTHR + threadIdx.x; pi < np; pi += STRIDE) {
        // Steady state: prefetch the window two iterations ahead.
        pf_window(Lc8, Ec8, Mc8, (pi - lane) + 2 * STRIDE, np, lane);

        float4 La = ldcs4(&L4[3 * pi + 0]);
        float4 Lb = ldcs4(&L4[3 * pi + 1]);
        float4 Lc = ldcs4(&L4[3 * pi + 2]);
        float4 Ea = ldcs4(&E4[3 * pi + 0]);
        float4 Eb = ldcs4(&E4[3 * pi + 1]);
        float4 Ec = ldcs4(&E4[3 * pi + 2]);
        int2 mw = ldcs2i(&M2[pi]);
        proc(La.x, La.y, La.z, La.w, Lb.x, Lb.y,
             Ea.x, Ea.y, Ea.z, Ea.w, Eb.x, Eb.y, mw.x, a);
        proc(Lb.z, Lb.w, Lc.x, Lc.y, Lc.z, Lc.w,
             Eb.z, Eb.w, Ec.x, Ec.y, Ec.z, Ec.w, mw.y, a);
        c0 += (mw.x == 0) + (mw.y == 0);
    }
    // Odd-B tail (not hit for B=4194304, kept for generality)
    if ((B & 1) && blockIdx.x == 0 && threadIdx.x == 0) {
        int i = B - 1;
        const float* L = label + 6 * i;
        const float* E = est   + 6 * i;
        int m = mix[i];
        proc(L[0], L[1], L[2], L[3], L[4], L[5],
             E[0], E[1], E[2], E[3], E[4], E[5], m, a);
        c0 += (m == 0);
    }

    // Deterministic block reduction -> per-block float partials.
    float v[5] = {a.S, a.M, a.A1, a.A2, (float)c0};
    __shared__ float sh[5][NTHR / 32];
    #pragma unroll
    for (int k = 0; k < 5; k++) {
        float x = v[k];
        #pragma unroll
        for (int o = 16; o; o >>= 1) x += __shfl_down_sync(0xffffffffu, x, o);
        if ((threadIdx.x & 31) == 0) sh[k][threadIdx.x >> 5] = x;
    }
    __syncthreads();
    if (threadIdx.x < 5) {
        float s = 0.f;
        #pragma unroll
        for (int j = 0; j < NTHR / 32; j++) s += sh[threadIdx.x][j];
        g_part[threadIdx.x][blockIdx.x] = s;
    }

    // ---- last-block-done finalize (deterministic fixed-order re-reduce) ----
    __shared__ int is_last;
    __threadfence();                     // publish g_part before the count
    if (threadIdx.x == 0) {
        int prev = atomicAdd(&g_count, 1);
        is_last = (prev == NBLK - 1);
    }
    __syncthreads();
    if (!is_last) return;
    __threadfence();                     // acquire all blocks' g_part

    // Float accumulation (tree-structured; rel err ~1e-6, tol is 1e-3).
    float v5[5] = {0.f, 0.f, 0.f, 0.f, 0.f};
    for (int i = threadIdx.x; i < NBLK; i += NTHR) {
        #pragma unroll
        for (int k = 0; k < 5; k++) v5[k] += g_part[k][i];
    }
    __shared__ float shf[5][NTHR / 32];
    #pragma unroll
    for (int k = 0; k < 5; k++) {
        float x = v5[k];
        #pragma unroll
        for (int o = 16; o; o >>= 1) x += __shfl_down_sync(0xffffffffu, x, o);
        if ((threadIdx.x & 31) == 0) shf[k][threadIdx.x >> 5] = x;
    }
    __syncthreads();
    if (threadIdx.x == 0) {
        double t[5];
        #pragma unroll
        for (int k = 0; k < 5; k++) {
            float s = 0.f;
            #pragma unroll
            for (int j = 0; j < NTHR / 32; j++) s += shf[k][j];
            t[k] = (double)s;
        }
        double Bn = (double)B;
        double single = t[0] / (3.0 * Bn);                   // S / (3B)
        out[0] = (float)((t[4] * single + t[1] / 3.0) / Bn); // label_loss
        out[1] = (float)(t[2] / Bn);                         // mae1
        out[2] = (float)(t[3] / Bn);                         // mae2
        g_count = 0;                     // reset for next graph replay
    }
}

extern "C" void kernel_launch(void* const* d_in, const int* in_sizes, int n_in,
                              void* d_out, int out_size)
{
    const float* label = (const float*)d_in[0];
    const float* est   = (const float*)d_in[1];
    const int*   mix   = (const int*)d_in[2];
    int B = in_sizes[2];  // mix_way element count

    fused_kernel<<<NBLK, NTHR>>>(label, est, mix, (float*)d_out, B);
}

// round 12
// speedup vs baseline: 1.1750x; 1.1750x over previous
#include <cuda_runtime.h>
#include <cuda_bf16.h>

// ---------------------------------------------------------------------------
// label_loss: B=4.19M elements -> 3 scalars. Memory-bound (218 MB read).
// R12: exact R10 champion structure (distance-1 L2 prefetch, 39.1us) with:
//  (a) prefetch issued AFTER the demand loads (in-order LSU: don't delay
//      the loads this warp is about to stall on),
//  (b) prefetch base pointers advanced by constant stride (no per-iter IMAD).
// R11 lesson: prefetch distance is peaked at 1 -- distance-2 regressed to
// 41.5us (long L2 residency -> evict-before-use under the .cs stream).
// ---------------------------------------------------------------------------

#define NBLK 888        // 148 SMs * 6 CTAs -> one wave
#define NTHR 256
#define STRIDE (NBLK * NTHR)

static __device__ float g_part[5][NBLK];   // SoA: coalesced finalize reads
static __device__ int   g_count = 0;       // reset by the finalizing block

__device__ __forceinline__ float4 ldcs4(const float4* p) {
    float4 v;
    asm volatile("ld.global.cs.v4.f32 {%0,%1,%2,%3}, [%4];"
                 : "=f"(v.x), "=f"(v.y), "=f"(v.z), "=f"(v.w) : "l"(p));
    return v;
}

__device__ __forceinline__ int2 ldcs2i(const int2* p) {
    int2 v;
    asm volatile("ld.global.cs.v2.s32 {%0,%1}, [%2];"
                 : "=r"(v.x), "=r"(v.y) : "l"(p));
    return v;
}

__device__ __forceinline__ float angdiff_deg(float x1, float y1, float x2, float y2) {
    // |atan2(y1,x1) - atan2(y2,x2)| wrapped to [0, 180], in degrees.
    float cr = fmaf(y1, x2, -x1 * y2);
    float dt = fmaf(x1, x2,  y1 * y2);
    float p  = fabsf(cr);
    float q  = fabsf(dt);
    float mx = fmaxf(fmaxf(p, q), 1e-38f);
    float mn = fminf(p, q);
    float r  = __fdividef(mn, mx);       // r in [0, 1]
    float t2 = r * r;
    const float D = 57.29577951308232f;  // rad -> deg folded into coefficients
    float pl;
    pl = fmaf(t2, -0.01172120f * D,  0.05265332f * D);
    pl = fmaf(t2, pl,           -0.11643287f * D);
    pl = fmaf(t2, pl,            0.19354346f * D);
    pl = fmaf(t2, pl,           -0.33262347f * D);
    pl = fmaf(t2, pl,            0.99997726f * D);
    float at = r * pl;                   // atan(mn/mx) in degrees, [0, 45]
    float a  = (p > q)      ? (90.0f  - at) : at;
    a        = (dt < 0.0f)  ? (180.0f - a ) : a;
    return a;
}

struct Acc { float S, M, A1, A2; };

__device__ __forceinline__ void proc(
    float l00, float l01, float l10, float l11, float l20, float l21,
    float e0, float e1, float e2, float e3, float e4, float e5,
    int m, Acc& a)
{
    float d0 = e0 - l00, d1 = e1 - l10, d2 = e2 - l20;
    float s11 = fmaf(d2, d2, fmaf(d1, d1, d0 * d0));
    float f0 = e3 - l01, f1 = e4 - l11, f2 = e5 - l21;
    float s22 = fmaf(f2, f2, fmaf(f1, f1, f0 * f0));
    float g0 = e0 - l01, g1 = e1 - l11, g2 = e2 - l21;
    float s12 = fmaf(g2, g2, fmaf(g1, g1, g0 * g0));
    float h0 = e3 - l00, h1 = e4 - l10, h2 = e5 - l20;
    float s21 = fmaf(h2, h2, fmaf(h1, h1, h0 * h0));

    a.S += s11;
    float mixed = fminf(s11 + s22, s12 + s21);  // /3 deferred to finalize
    a.M  += (m != 0) ? mixed : 0.0f;

    float a11 = angdiff_deg(l00, l10, e0, e1);
    float a22 = angdiff_deg(l01, l11, e3, e4);
    float a12 = angdiff_deg(l00, l10, e3, e4);
    float a21 = angdiff_deg(l01, l11, e0, e1);
    bool ud = (a11 + a22) < (a12 + a21);
    a.A1 += ud ? a11 : a12;
    a.A2 += ud ? a22 : a21;
}

__global__ void __launch_bounds__(NTHR, 6)
fused_kernel(const float* __restrict__ label, const float* __restrict__ est,
             const int* __restrict__ mix, float* __restrict__ out, int B)
{
    Acc a{0.f, 0.f, 0.f, 0.f};
    int c0 = 0;
    const float4* L4 = (const float4*)label;
    const float4* E4 = (const float4*)est;
    const int2*   M2 = (const int2*)mix;
    int np = B >> 1;  // pairs; 2 elements = 3 float4 per array
    const int lane = threadIdx.x & 31;
    const int wb0 = blockIdx.x * NTHR + (threadIdx.x & ~31);  // warp base pair

    // Per-lane prefetch pointer for the NEXT iteration's warp window,
    // advanced by a constant stride each iteration (no per-iter IMAD).
    // Window: label = 12 x 128B lines, est = 12 lines, mix = 2 lines.
    const bool pf_on = (lane < 26);
    const char* pf_ptr;
    size_t pf_step;
    {
        int wbn = wb0 + STRIDE;          // first prefetch target (iter 1)
        size_t o48 = (size_t)wbn * 48;
        if (lane < 12) {
            pf_ptr  = (const char*)label + o48 + (size_t)lane * 128;
            pf_step = (size_t)STRIDE * 48;
        } else if (lane < 24) {
            pf_ptr  = (const char*)est + o48 + (size_t)(lane - 12) * 128;
            pf_step = (size_t)STRIDE * 48;
        } else {
            pf_ptr  = (const char*)mix + (size_t)wbn * 8 + (size_t)(lane - 24) * 128;
            pf_step = (size_t)STRIDE * 8;
        }
    }

    for (int pi = blockIdx.x * NTHR + threadIdx.x; pi < np; pi += STRIDE) {
        // Demand loads first (in-order LSU: don't delay them with prefetch).
        float4 La = ldcs4(&L4[3 * pi + 0]);
        float4 Lb = ldcs4(&L4[3 * pi + 1]);
        float4 Lc = ldcs4(&L4[3 * pi + 2]);
        float4 Ea = ldcs4(&E4[3 * pi + 0]);
        float4 Eb = ldcs4(&E4[3 * pi + 1]);
        float4 Ec = ldcs4(&E4[3 * pi + 2]);
        int2 mw = ldcs2i(&M2[pi]);

        // L2 prefetch of next iteration's warp window (distance 1).
        if (pf_on && (pi - lane) + STRIDE + 32 <= np)
            asm volatile("prefetch.global.L2 [%0];" :: "l"(pf_ptr));
        pf_ptr += pf_step;

        proc(La.x, La.y, La.z, La.w, Lb.x, Lb.y,
             Ea.x, Ea.y, Ea.z, Ea.w, Eb.x, Eb.y, mw.x, a);
        proc(Lb.z, Lb.w, Lc.x, Lc.y, Lc.z, Lc.w,
             Eb.z, Eb.w, Ec.x, Ec.y, Ec.z, Ec.w, mw.y, a);
        c0 += (mw.x == 0) + (mw.y == 0);
    }
    // Odd-B tail (not hit for B=4194304, kept for generality)
    if ((B & 1) && blockIdx.x == 0 && threadIdx.x == 0) {
        int i = B - 1;
        const float* L = label + 6 * i;
        const float* E = est   + 6 * i;
        int m = mix[i];
        proc(L[0], L[1], L[2], L[3], L[4], L[5],
             E[0], E[1], E[2], E[3], E[4], E[5], m, a);
        c0 += (m == 0);
    }

    // Deterministic block reduction -> per-block float partials.
    float v[5] = {a.S, a.M, a.A1, a.A2, (float)c0};
    __shared__ float sh[5][NTHR / 32];
    #pragma unroll
    for (int k = 0; k < 5; k++) {
        float x = v[k];
        #pragma unroll
        for (int o = 16; o; o >>= 1) x += __shfl_down_sync(0xffffffffu, x, o);
        if ((threadIdx.x & 31) == 0) sh[k][threadIdx.x >> 5] = x;
    }
    __syncthreads();
    if (threadIdx.x < 5) {
        float s = 0.f;
        #pragma unroll
        for (int j = 0; j < NTHR / 32; j++) s += sh[threadIdx.x][j];
        g_part[threadIdx.x][blockIdx.x] = s;
    }

    // ---- last-block-done finalize (deterministic fixed-order re-reduce) ----
    __shared__ int is_last;
    __threadfence();                     // publish g_part before the count
    if (threadIdx.x == 0) {
        int prev = atomicAdd(&g_count, 1);
        is_last = (prev == NBLK - 1);
    }
    __syncthreads();
    if (!is_last) return;
    __threadfence();                     // acquire all blocks' g_part

    // Float accumulation (tree-structured; rel err ~1e-6, tol is 1e-3).
    float v5[5] = {0.f, 0.f, 0.f, 0.f, 0.f};
    for (int i = threadIdx.x; i < NBLK; i += NTHR) {
        #pragma unroll
        for (int k = 0; k < 5; k++) v5[k] += g_part[k][i];
    }
    __shared__ float shf[5][NTHR / 32];
    #pragma unroll
    for (int k = 0; k < 5; k++) {
        float x = v5[k];
        #pragma unroll
        for (int o = 16; o; o >>= 1) x += __shfl_down_sync(0xffffffffu, x, o);
        if ((threadIdx.x & 31) == 0) shf[k][threadIdx.x >> 5] = x;
    }
    __syncthreads();
    if (threadIdx.x == 0) {
        double t[5];
        #pragma unroll
        for (int k = 0; k < 5; k++) {
            float s = 0.f;
            #pragma unroll
            for (int j = 0; j < NTHR / 32; j++) s += shf[k][j];
            t[k] = (double)s;
        }
        double Bn = (double)B;
        double single = t[0] / (3.0 * Bn);                   // S / (3B)
        out[0] = (float)((t[4] * single + t[1] / 3.0) / Bn); // label_loss
        out[1] = (float)(t[2] / Bn);                         // mae1
        out[2] = (float)(t[3] / Bn);                         // mae2
        g_count = 0;                     // reset for next graph replay
    }
}

extern "C" void kernel_launch(void* const* d_in, const int* in_sizes, int n_in,
                              void* d_out, int out_size)
{
    const float* label = (const float*)d_in[0];
    const float* est   = (const float*)d_in[1];
    const int*   mix   = (const int*)d_in[2];
    int B = in_sizes[2];  // mix_way element count

    fused_kernel<<<NBLK, NTHR>>>(label, est, mix, (float*)d_out, B);
}